// round 15
// baseline (speedup 1.0000x reference)
#include <cuda_runtime.h>
#include <math_constants.h>

#define E_TOTAL 500000
#define D 128
#define B 64
#define N_ITERS 3

#define ATT_BLOCKS 512
#define ATT_THREADS 256
#define N_WARPS (ATT_BLOCKS * ATT_THREADS / 32)   /* 4096 */
#define EPW ((E_TOTAL + N_WARPS - 1) / N_WARPS)   /* 123  */
#define MAX_SLOTS 4
#define PTOT (N_WARPS * MAX_SLOTS)                /* 16384 */
#define MAXL 512

// ---------------- persistent device scratch (no allocations) ----------------
__device__ __align__(16) float g_h[B * D];
__device__ __align__(16) float g_c[B * D];
__device__ __align__(16) float g_qstar[B * 2 * D];
__device__ float g_bias[4 * D];
__device__ float g_wT_ih[2 * D * 4 * D];   // [256][512], k-major
__device__ float g_wT_hh[D * 4 * D];       // [128][512], k-major
__device__ int   g_pseg[PTOT];
__device__ float g_pm[PTOT];
__device__ float g_ps[PTOT];
__device__ __align__(16) float g_pr[(size_t)PTOT * D];   // 8 MB

// ---------------- init: zero state, fold bias, transpose weights ------------
__global__ void init_kernel(const float* __restrict__ w_ih,
                            const float* __restrict__ w_hh,
                            const float* __restrict__ b_ih,
                            const float* __restrict__ b_hh) {
    int t = blockIdx.x * blockDim.x + threadIdx.x;
    if (t < 4 * D) g_bias[t] = b_ih[t] + b_hh[t];
    if (t < B * D) { g_h[t] = 0.f; g_c[t] = 0.f; }
    if (t < B * 2 * D) g_qstar[t] = 0.f;
    if (t < 4 * D * 2 * D) {               // 512*256 = 131072
        int j = t / (2 * D), k = t % (2 * D);
        g_wT_ih[k * (4 * D) + j] = w_ih[t];
    }
    if (t < 4 * D * D) {                   // 512*128 = 65536
        int j = t / D, k = t % D;
        g_wT_hh[k * (4 * D) + j] = w_hh[t];
    }
}

// ---------------- LSTM cell: one block per batch row, 512 threads -----------
__device__ __forceinline__ float sigmoidf_(float x) {
    return 1.f / (1.f + __expf(-x));
}

__global__ void lstm_kernel() {
    int b = blockIdx.x;
    int j = threadIdx.x;                    // 0..511  (one gate element)
    __shared__ float x[2 * D];
    __shared__ float hh[D];
    __shared__ float gsh[4 * D];
    if (j < 2 * D) x[j] = g_qstar[b * 2 * D + j];
    if (j < D)     hh[j] = g_h[b * D + j];
    __syncthreads();

    float acc = g_bias[j];
#pragma unroll 4
    for (int k = 0; k < 2 * D; ++k) acc += x[k] * g_wT_ih[k * (4 * D) + j];
#pragma unroll 4
    for (int k = 0; k < D; ++k)     acc += hh[k] * g_wT_hh[k * (4 * D) + j];
    gsh[j] = acc;
    __syncthreads();

    if (j < D) {
        float ig = gsh[j];
        float fg = gsh[D + j];
        float gg = gsh[2 * D + j];
        float og = gsh[3 * D + j];
        float cn = sigmoidf_(fg) * g_c[b * D + j] + sigmoidf_(ig) * tanhf(gg);
        float hn = sigmoidf_(og) * tanhf(cn);
        g_c[b * D + j] = cn;
        g_h[b * D + j] = hn;
    }
}

// ---------------- fused attention pass: online softmax per segment ----------
__global__ void attn_kernel(const float4* __restrict__ feat4,
                            const int* __restrict__ eb) {
    const int gtid = blockIdx.x * blockDim.x + threadIdx.x;
    const int wid  = gtid >> 5;
    const int lane = gtid & 31;

    // every warp re-initializes its partial slots each invocation
    if (lane < MAX_SLOTS) g_pseg[wid * MAX_SLOTS + lane] = -1;

    int e0 = wid * EPW;
    if (e0 >= E_TOTAL) return;
    int e1 = min(E_TOTAL, e0 + EPW);

    const float4* q4 = (const float4*)g_h;

    int   cur  = eb[e0];
    int   slot = 0;
    float m = -CUDART_INF_F, s = 0.f;
    float4 r = make_float4(0.f, 0.f, 0.f, 0.f);

    for (int e = e0; e < e1; ++e) {
        int seg = eb[e];
        float4 f  = __ldcs(feat4 + (size_t)e * 32 + lane);   // streaming
        float4 qv = q4[seg * 32 + lane];                     // L1-resident
        float p = f.x * qv.x + f.y * qv.y + f.z * qv.z + f.w * qv.w;
#pragma unroll
        for (int off = 16; off; off >>= 1)
            p += __shfl_xor_sync(0xffffffffu, p, off);

        if (seg != cur) {                                    // flush partial
            int idx = wid * MAX_SLOTS + slot;
            if (lane == 0) { g_pseg[idx] = cur; g_pm[idx] = m; g_ps[idx] = s; }
            ((float4*)g_pr)[(size_t)idx * 32 + lane] = r;
            slot = min(slot + 1, MAX_SLOTS - 1);
            cur = seg; m = -CUDART_INF_F; s = 0.f;
            r = make_float4(0.f, 0.f, 0.f, 0.f);
        }
        // online softmax update
        float nm   = fmaxf(m, p);
        float corr = __expf(m - nm);    // m==-inf -> 0
        float w    = __expf(p - nm);
        s   = s * corr + w;
        r.x = fmaf(f.x, w, r.x * corr);
        r.y = fmaf(f.y, w, r.y * corr);
        r.z = fmaf(f.z, w, r.z * corr);
        r.w = fmaf(f.w, w, r.w * corr);
        m = nm;
    }
    // final flush
    int idx = wid * MAX_SLOTS + slot;
    if (lane == 0) { g_pseg[idx] = cur; g_pm[idx] = m; g_ps[idx] = s; }
    ((float4*)g_pr)[(size_t)idx * 32 + lane] = r;
}

// ---------------- combine partials per segment, emit q_star -----------------
__global__ void combine_kernel(float* __restrict__ out, int last) {
    const int seg = blockIdx.x;
    const int tid = threadIdx.x;            // 256 threads
    __shared__ int   list[MAXL];
    __shared__ float scl[MAXL];
    __shared__ float red[256];
    __shared__ int   cnt;
    if (tid == 0) cnt = 0;
    __syncthreads();

    for (int i = tid; i < PTOT; i += 256)
        if (g_pseg[i] == seg) {
            int p = atomicAdd(&cnt, 1);
            if (p < MAXL) list[p] = i;
        }
    __syncthreads();
    int n = min(cnt, MAXL);

    // global max over this segment's partials
    float m = -CUDART_INF_F;
    for (int i = tid; i < n; i += 256) m = fmaxf(m, g_pm[list[i]]);
    red[tid] = m; __syncthreads();
    for (int st = 128; st; st >>= 1) {
        if (tid < st) red[tid] = fmaxf(red[tid], red[tid + st]);
        __syncthreads();
    }
    float M = red[0];
    __syncthreads();

    // scales and S
    float sp = 0.f;
    for (int i = tid; i < n; i += 256) {
        float sc = __expf(g_pm[list[i]] - M);
        scl[i] = sc;
        sp += g_ps[list[i]] * sc;
    }
    red[tid] = sp; __syncthreads();
    for (int st = 128; st; st >>= 1) {
        if (tid < st) red[tid] += red[tid + st];
        __syncthreads();
    }
    float S = red[0];
    __syncthreads();

    float* dst = last ? out : g_qstar;
    if (tid < D) {
        float R = 0.f;
        for (int i = 0; i < n; ++i)
            R = fmaf(g_pr[(size_t)list[i] * D + tid], scl[i], R);
        dst[seg * 2 * D + D + tid] = R / (S + 1e-8f);   // readout
        dst[seg * 2 * D + tid]     = g_h[seg * D + tid]; // q = h
    }
}

// ---------------- launch ----------------------------------------------------
extern "C" void kernel_launch(void* const* d_in, const int* in_sizes, int n_in,
                              void* d_out, int out_size) {
    const float* feat  = (const float*)d_in[0];
    const int*   eb    = (const int*)d_in[1];
    const float* w_ih  = (const float*)d_in[2];
    const float* w_hh  = (const float*)d_in[3];
    const float* b_ih  = (const float*)d_in[4];
    const float* b_hh  = (const float*)d_in[5];
    float* out = (float*)d_out;

    init_kernel<<<512, 256>>>(w_ih, w_hh, b_ih, b_hh);
    for (int it = 0; it < N_ITERS; ++it) {
        lstm_kernel<<<B, 4 * D>>>();
        attn_kernel<<<ATT_BLOCKS, ATT_THREADS>>>((const float4*)feat, eb);
        combine_kernel<<<B, 256>>>(out, it == N_ITERS - 1 ? 1 : 0);
    }
    (void)in_sizes; (void)n_in; (void)out_size;
}

// round 16
// speedup vs baseline: 1.0062x; 1.0062x over previous
#include <cuda_runtime.h>
#include <math_constants.h>

#define E_TOTAL 500000
#define D 128
#define B 64
#define N_ITERS 3

#define ATT_BLOCKS 512
#define ATT_THREADS 256
#define N_WARPS (ATT_BLOCKS * ATT_THREADS / 32)   /* 4096 */
#define EPW ((E_TOTAL + N_WARPS - 1) / N_WARPS)   /* 123  */
#define MAX_SLOTS 4
#define PTOT (N_WARPS * MAX_SLOTS)                /* 16384 */
#define MAXL 512

// ---------------- persistent device scratch (no allocations) ----------------
__device__ __align__(16) float g_h[B * D];
__device__ __align__(16) float g_c[B * D];
__device__ __align__(16) float g_qstar[B * 2 * D];
__device__ float g_bias[4 * D];
__device__ float g_wT_ih[2 * D * 4 * D];   // [256][512], k-major
__device__ float g_wT_hh[D * 4 * D];       // [128][512], k-major
__device__ int   g_pseg[PTOT];
__device__ float g_pm[PTOT];
__device__ float g_ps[PTOT];
__device__ __align__(16) float g_pr[(size_t)PTOT * D];   // 8 MB

// ---------------- init: zero state, fold bias, transpose weights ------------
__global__ void init_kernel(const float* __restrict__ w_ih,
                            const float* __restrict__ w_hh,
                            const float* __restrict__ b_ih,
                            const float* __restrict__ b_hh) {
    int t = blockIdx.x * blockDim.x + threadIdx.x;
    if (t < 4 * D) g_bias[t] = b_ih[t] + b_hh[t];
    if (t < B * D) { g_h[t] = 0.f; g_c[t] = 0.f; }
    if (t < B * 2 * D) g_qstar[t] = 0.f;
    if (t < 4 * D * 2 * D) {               // 512*256 = 131072
        int j = t / (2 * D), k = t % (2 * D);
        g_wT_ih[k * (4 * D) + j] = w_ih[t];
    }
    if (t < 4 * D * D) {                   // 512*128 = 65536
        int j = t / D, k = t % D;
        g_wT_hh[k * (4 * D) + j] = w_hh[t];
    }
}

// ---------------- LSTM cell: one block per batch row, 512 threads -----------
__device__ __forceinline__ float sigmoidf_(float x) {
    return 1.f / (1.f + __expf(-x));
}

__global__ void lstm_kernel() {
    int b = blockIdx.x;
    int j = threadIdx.x;                    // 0..511  (one gate element)
    __shared__ float x[2 * D];
    __shared__ float hh[D];
    __shared__ float gsh[4 * D];
    if (j < 2 * D) x[j] = g_qstar[b * 2 * D + j];
    if (j < D)     hh[j] = g_h[b * D + j];
    __syncthreads();

    float acc = g_bias[j];
#pragma unroll 4
    for (int k = 0; k < 2 * D; ++k) acc += x[k] * g_wT_ih[k * (4 * D) + j];
#pragma unroll 4
    for (int k = 0; k < D; ++k)     acc += hh[k] * g_wT_hh[k * (4 * D) + j];
    gsh[j] = acc;
    __syncthreads();

    if (j < D) {
        float ig = gsh[j];
        float fg = gsh[D + j];
        float gg = gsh[2 * D + j];
        float og = gsh[3 * D + j];
        float cn = sigmoidf_(fg) * g_c[b * D + j] + sigmoidf_(ig) * tanhf(gg);
        float hn = sigmoidf_(og) * tanhf(cn);
        g_c[b * D + j] = cn;
        g_h[b * D + j] = hn;
    }
}

// ---------------- fused attention pass: online softmax per segment ----------
__global__ void attn_kernel(const float4* __restrict__ feat4,
                            const int* __restrict__ eb) {
    const int gtid = blockIdx.x * blockDim.x + threadIdx.x;
    const int wid  = gtid >> 5;
    const int lane = gtid & 31;

    // every warp re-initializes its partial slots each invocation
    if (lane < MAX_SLOTS) g_pseg[wid * MAX_SLOTS + lane] = -1;

    int e0 = wid * EPW;
    if (e0 >= E_TOTAL) return;
    int e1 = min(E_TOTAL, e0 + EPW);

    const float4* q4 = (const float4*)g_h;

    int   cur  = eb[e0];
    int   slot = 0;
    float m = -CUDART_INF_F, s = 0.f;
    float4 r = make_float4(0.f, 0.f, 0.f, 0.f);

    for (int e = e0; e < e1; ++e) {
        int seg = eb[e];
        float4 f  = __ldcs(feat4 + (size_t)e * 32 + lane);   // streaming
        float4 qv = q4[seg * 32 + lane];                     // L1-resident
        float p = f.x * qv.x + f.y * qv.y + f.z * qv.z + f.w * qv.w;
#pragma unroll
        for (int off = 16; off; off >>= 1)
            p += __shfl_xor_sync(0xffffffffu, p, off);

        if (seg != cur) {                                    // flush partial
            int idx = wid * MAX_SLOTS + slot;
            if (lane == 0) { g_pseg[idx] = cur; g_pm[idx] = m; g_ps[idx] = s; }
            ((float4*)g_pr)[(size_t)idx * 32 + lane] = r;
            slot = min(slot + 1, MAX_SLOTS - 1);
            cur = seg; m = -CUDART_INF_F; s = 0.f;
            r = make_float4(0.f, 0.f, 0.f, 0.f);
        }
        // online softmax update
        float nm   = fmaxf(m, p);
        float corr = __expf(m - nm);    // m==-inf -> 0
        float w    = __expf(p - nm);
        s   = s * corr + w;
        r.x = fmaf(f.x, w, r.x * corr);
        r.y = fmaf(f.y, w, r.y * corr);
        r.z = fmaf(f.z, w, r.z * corr);
        r.w = fmaf(f.w, w, r.w * corr);
        m = nm;
    }
    // final flush
    int idx = wid * MAX_SLOTS + slot;
    if (lane == 0) { g_pseg[idx] = cur; g_pm[idx] = m; g_ps[idx] = s; }
    ((float4*)g_pr)[(size_t)idx * 32 + lane] = r;
}

// ---------------- combine partials per segment, emit q_star -----------------
__global__ void combine_kernel(float* __restrict__ out, int last) {
    const int seg = blockIdx.x;
    const int tid = threadIdx.x;            // 256 threads
    __shared__ int   list[MAXL];
    __shared__ float scl[MAXL];
    __shared__ float red[256];
    __shared__ int   cnt;
    if (tid == 0) cnt = 0;
    __syncthreads();

    for (int i = tid; i < PTOT; i += 256)
        if (g_pseg[i] == seg) {
            int p = atomicAdd(&cnt, 1);
            if (p < MAXL) list[p] = i;
        }
    __syncthreads();
    int n = min(cnt, MAXL);

    // global max over this segment's partials
    float m = -CUDART_INF_F;
    for (int i = tid; i < n; i += 256) m = fmaxf(m, g_pm[list[i]]);
    red[tid] = m; __syncthreads();
    for (int st = 128; st; st >>= 1) {
        if (tid < st) red[tid] = fmaxf(red[tid], red[tid + st]);
        __syncthreads();
    }
    float M = red[0];
    __syncthreads();

    // scales and S
    float sp = 0.f;
    for (int i = tid; i < n; i += 256) {
        float sc = __expf(g_pm[list[i]] - M);
        scl[i] = sc;
        sp += g_ps[list[i]] * sc;
    }
    red[tid] = sp; __syncthreads();
    for (int st = 128; st; st >>= 1) {
        if (tid < st) red[tid] += red[tid + st];
        __syncthreads();
    }
    float S = red[0];
    __syncthreads();

    float* dst = last ? out : g_qstar;
    if (tid < D) {
        float R = 0.f;
        for (int i = 0; i < n; ++i)
            R = fmaf(g_pr[(size_t)list[i] * D + tid], scl[i], R);
        dst[seg * 2 * D + D + tid] = R / (S + 1e-8f);   // readout
        dst[seg * 2 * D + tid]     = g_h[seg * D + tid]; // q = h
    }
}

// ---------------- launch ----------------------------------------------------
extern "C" void kernel_launch(void* const* d_in, const int* in_sizes, int n_in,
                              void* d_out, int out_size) {
    const float* feat  = (const float*)d_in[0];
    const int*   eb    = (const int*)d_in[1];
    const float* w_ih  = (const float*)d_in[2];
    const float* w_hh  = (const float*)d_in[3];
    const float* b_ih  = (const float*)d_in[4];
    const float* b_hh  = (const float*)d_in[5];
    float* out = (float*)d_out;

    init_kernel<<<512, 256>>>(w_ih, w_hh, b_ih, b_hh);
    for (int it = 0; it < N_ITERS; ++it) {
        lstm_kernel<<<B, 4 * D>>>();
        attn_kernel<<<ATT_BLOCKS, ATT_THREADS>>>((const float4*)feat, eb);
        combine_kernel<<<B, 256>>>(out, it == N_ITERS - 1 ? 1 : 0);
    }
    (void)in_sizes; (void)n_in; (void)out_size;
}